// round 15
// baseline (speedup 1.0000x reference)
#include <cuda_runtime.h>

#define N_ROWS 16384
#define D      2048
#define D4     (D / 4)              // 512 float4 per row
#define NUM_CAMS   8
#define S      8192                 // 1024 labels x 8 cams
#define SLOT_CAP 24                 // P(Poisson(2) > 24) ~ 1e-16; fallback exists
#define TPB    256
#define NBLK   740                  // 148 SMs x 5 CTAs @ 48 regs -> one wave
#define NPREP  64                   // prep CTAs (blockIdx 0..63)
#define NWARPS (NBLK * (TPB / 32))

// ---- scratch (device globals; invariant: counters/flags zero at entry,
// ---- restored by the last block at the end of every run) ----
__device__ int      g_count[S];
__device__ int      g_slots[S * SLOT_CAP];
__device__ int      g_seg[N_ROWS];
__device__ int2     g_d2[S];
__device__ int4     g_d3[S];
__device__ int4     g_d4[S];
__device__ int      g_big[S];
__device__ int      g_n2, g_n3, g_n4, g_nbig;
__device__ int      g_done;
__device__ int      g_ready;        // 0 between runs; 1 = descriptors final
__device__ double   g_partial[NBLK];
__device__ int      g_bar_count;    // stays 0 between runs
__device__ unsigned g_bar_gen;      // monotonically grows; never reset

// Barrier among the NPREP prep blocks only. Safe: they are in the first
// scheduled wave (64 << any wave), hence co-resident.
__device__ __forceinline__ void prep_barrier() {
    __syncthreads();
    if (threadIdx.x == 0) {
        unsigned gen = *(volatile unsigned*)&g_bar_gen;   // read BEFORE arrive
        __threadfence();
        if (atomicAdd(&g_bar_count, 1) == NPREP - 1) {
            g_bar_count = 0;
            __threadfence();
            atomicAdd(&g_bar_gen, 1u);
        } else {
            while (*(volatile unsigned*)&g_bar_gen == gen) { }
        }
        __threadfence();
    }
    __syncthreads();
}

__device__ __forceinline__ float sl1(float d) {
    float ad = fabsf(d);
    return ad < 1.0f ? 0.5f * d * d : ad - 0.5f;
}
__device__ __forceinline__ float sl1_4(float4 a, float4 m) {
    return sl1(a.x - m.x) + sl1(a.y - m.y) + sl1(a.z - m.z) + sl1(a.w - m.w);
}
__device__ __forceinline__ void acc4(float4& s, float4 a) {
    s.x += a.x; s.y += a.y; s.z += a.z; s.w += a.w;
}
// cnt==2 symmetry: both rows contribute sl1(+-(a-b)/2) -> 2x one evaluation
__device__ __forceinline__ float sl1_4_half(float4 a, float4 b) {
    return 2.0f * (sl1(0.5f * (a.x - b.x)) + sl1(0.5f * (a.y - b.y)) +
                   sl1(0.5f * (a.z - b.z)) + sl1(0.5f * (a.w - b.w)));
}

// ---------------------------------------------------------------------------
// Single fused kernel.
//  blockIdx 0..63 : prep (probe, histogram+slots, 64-barrier, pack, 64-barrier,
//                   release g_ready). Other CTAs: nanosleep-poll g_ready — a
//                   ONE-DIRECTIONAL wait on first-wave blocks, so safe at any
//                   occupancy (late blocks see the flag already set).
//  All CTAs then run the flat warp-item stream (BIG/D4/D3/D2, exact loads).
//  Last finishing block: final reduction, output, scratch reset.
// ---------------------------------------------------------------------------
__global__ __launch_bounds__(TPB) void k_all(const float* __restrict__ feats,
                                             const int* __restrict__ lab32,
                                             const int* __restrict__ cam32,
                                             float* __restrict__ out) {
    __shared__ float wsum[TPB / 32];
    __shared__ bool  s_last;
    int t = threadIdx.x;
    int lane = t & 31;
    const float4* __restrict__ F = (const float4*)feats;

    if (blockIdx.x < NPREP) {
        // ---- prep phase A: layout probe + histogram + slot insertion ------
        __shared__ int s_any;
        if (t == 0) s_any = 0;
        __syncthreads();
        // Odd int32 words of little-endian int64 cam_ids (values 0..7) are 0;
        // index 2t+1 < 512 is in-bounds under both layouts.
        int probe = cam32[2 * t + 1];
#pragma unroll
        for (int o = 16; o; o >>= 1)
            probe |= __shfl_xor_sync(0xffffffffu, probe, o);
        if (lane == 0 && probe) atomicOr(&s_any, 1);
        __syncthreads();
        int stride = s_any ? 1 : 2;        // int32 : int64

        int gtid = blockIdx.x * TPB + t;   // 0..16383 == N_ROWS
        int seg = lab32[gtid * stride] * NUM_CAMS + cam32[gtid * stride];
        g_seg[gtid] = seg;
        int pos = atomicAdd(&g_count[seg], 1);
        if (pos < SLOT_CAP) g_slots[seg * SLOT_CAP + pos] = gtid;

        prep_barrier();

        // ---- prep phase B: pack exact per-count descriptor lists ----------
        if (gtid < S) {
            int cnt = g_count[gtid];
            if (cnt >= 2) {
                const int* sl = g_slots + gtid * SLOT_CAP;
                if (cnt == 2)
                    g_d2[atomicAdd(&g_n2, 1)] = make_int2(sl[0], sl[1]);
                else if (cnt == 3)
                    g_d3[atomicAdd(&g_n3, 1)] = make_int4(sl[0], sl[1], sl[2], 0);
                else if (cnt == 4)
                    g_d4[atomicAdd(&g_n4, 1)] = make_int4(sl[0], sl[1], sl[2], sl[3]);
                else
                    g_big[atomicAdd(&g_nbig, 1)] = gtid;
            }
        }

        prep_barrier();                    // all packing visible

        if (blockIdx.x == 0 && t == 0) {
            __threadfence();
            *(volatile int*)&g_ready = 1;  // release
        }
    } else {
        // ---- workers: acquire-wait on the prep flag (backoff polling) -----
        if (t == 0) {
            while (*(volatile int*)&g_ready == 0) __nanosleep(128);
        }
        __syncthreads();
        __threadfence();                   // acquire ordering for descriptors
    }

    // =================== flat warp-item loss stream =========================
    int gw = blockIdx.x * (TPB / 32) + (t >> 5);
    float facc = 0.f;

    // ---- BIG: cnt >= 5, two-pass via slots (pass 2 = L1 hit), 256-col items
    {
        int nitems = g_nbig * 8;
        for (int u = gw; u < nitems; u += NWARPS) {
            int seg = g_big[u >> 3];
            int col = (u & 7) * 64 + lane;
            int cnt = g_count[seg];
            if (cnt <= SLOT_CAP) {
                const int* sl = g_slots + seg * SLOT_CAP;
                float4 s0 = make_float4(0.f, 0.f, 0.f, 0.f);
                float4 s1 = make_float4(0.f, 0.f, 0.f, 0.f);
                for (int k = 0; k < cnt; k++) {
                    const float4* p = F + (size_t)sl[k] * D4 + col;
                    acc4(s0, __ldg(p)); acc4(s1, __ldg(p + 32));
                }
                float inv = 1.0f / (float)cnt;
                float4 m0 = make_float4(s0.x*inv, s0.y*inv, s0.z*inv, s0.w*inv);
                float4 m1 = make_float4(s1.x*inv, s1.y*inv, s1.z*inv, s1.w*inv);
                for (int k = 0; k < cnt; k++) {
                    const float4* p = F + (size_t)sl[k] * D4 + col;
                    facc += sl1_4(__ldg(p), m0) + sl1_4(__ldg(p + 32), m1);
                }
            } else {                                   // ~1e-16 fallback
                float4 s0 = make_float4(0.f, 0.f, 0.f, 0.f);
                float4 s1 = make_float4(0.f, 0.f, 0.f, 0.f);
                for (int r = 0; r < N_ROWS; r++)
                    if (g_seg[r] == seg) {
                        const float4* p = F + (size_t)r * D4 + col;
                        acc4(s0, __ldg(p)); acc4(s1, __ldg(p + 32));
                    }
                float inv = 1.0f / (float)cnt;
                float4 m0 = make_float4(s0.x*inv, s0.y*inv, s0.z*inv, s0.w*inv);
                float4 m1 = make_float4(s1.x*inv, s1.y*inv, s1.z*inv, s1.w*inv);
                for (int r = 0; r < N_ROWS; r++)
                    if (g_seg[r] == seg) {
                        const float4* p = F + (size_t)r * D4 + col;
                        facc += sl1_4(__ldg(p), m0) + sl1_4(__ldg(p + 32), m1);
                    }
            }
        }
    }

    // ---- D4: cnt == 4, 8 exact LDG.128 in flight, 256-col items -----------
    {
        int nitems = g_n4 * 8;
        int u = gw;
        int4 dd = (u < nitems) ? g_d4[u >> 3] : make_int4(0, 0, 0, 0);
        while (u < nitems) {
            int un = u + NWARPS;
            int4 ddn = (un < nitems) ? g_d4[un >> 3] : dd;   // prefetch next
            int col = (u & 7) * 64 + lane;
            const float4* p0 = F + (size_t)dd.x * D4 + col;
            const float4* p1 = F + (size_t)dd.y * D4 + col;
            const float4* p2 = F + (size_t)dd.z * D4 + col;
            const float4* p3 = F + (size_t)dd.w * D4 + col;
            float4 a0 = __ldg(p0), b0 = __ldg(p0 + 32);
            float4 a1 = __ldg(p1), b1 = __ldg(p1 + 32);
            float4 a2 = __ldg(p2), b2 = __ldg(p2 + 32);
            float4 a3 = __ldg(p3), b3 = __ldg(p3 + 32);
            float4 m0 = make_float4(0.25f*(a0.x+a1.x+a2.x+a3.x), 0.25f*(a0.y+a1.y+a2.y+a3.y),
                                    0.25f*(a0.z+a1.z+a2.z+a3.z), 0.25f*(a0.w+a1.w+a2.w+a3.w));
            float4 m1 = make_float4(0.25f*(b0.x+b1.x+b2.x+b3.x), 0.25f*(b0.y+b1.y+b2.y+b3.y),
                                    0.25f*(b0.z+b1.z+b2.z+b3.z), 0.25f*(b0.w+b1.w+b2.w+b3.w));
            facc += sl1_4(a0, m0) + sl1_4(a1, m0) + sl1_4(a2, m0) + sl1_4(a3, m0);
            facc += sl1_4(b0, m1) + sl1_4(b1, m1) + sl1_4(b2, m1) + sl1_4(b3, m1);
            dd = ddn; u = un;
        }
    }

    // ---- D3: cnt == 3, 6 exact loads, 256-col items ------------------------
    {
        int nitems = g_n3 * 8;
        int u = gw;
        int4 dd = (u < nitems) ? g_d3[u >> 3] : make_int4(0, 0, 0, 0);
        const float third = 1.0f / 3.0f;
        while (u < nitems) {
            int un = u + NWARPS;
            int4 ddn = (un < nitems) ? g_d3[un >> 3] : dd;
            int col = (u & 7) * 64 + lane;
            const float4* p0 = F + (size_t)dd.x * D4 + col;
            const float4* p1 = F + (size_t)dd.y * D4 + col;
            const float4* p2 = F + (size_t)dd.z * D4 + col;
            float4 a0 = __ldg(p0), b0 = __ldg(p0 + 32);
            float4 a1 = __ldg(p1), b1 = __ldg(p1 + 32);
            float4 a2 = __ldg(p2), b2 = __ldg(p2 + 32);
            float4 m0 = make_float4(third*(a0.x+a1.x+a2.x), third*(a0.y+a1.y+a2.y),
                                    third*(a0.z+a1.z+a2.z), third*(a0.w+a1.w+a2.w));
            float4 m1 = make_float4(third*(b0.x+b1.x+b2.x), third*(b0.y+b1.y+b2.y),
                                    third*(b0.z+b1.z+b2.z), third*(b0.w+b1.w+b2.w));
            facc += sl1_4(a0, m0) + sl1_4(a1, m0) + sl1_4(a2, m0);
            facc += sl1_4(b0, m1) + sl1_4(b1, m1) + sl1_4(b2, m1);
            dd = ddn; u = un;
        }
    }

    // ---- D2: cnt == 2, 512-col items, symmetry halves the math ------------
    {
        int nitems = g_n2 * 4;
        int u = gw;
        int2 dd = (u < nitems) ? g_d2[u >> 2] : make_int2(0, 0);
        while (u < nitems) {
            int un = u + NWARPS;
            int2 ddn = (un < nitems) ? g_d2[un >> 2] : dd;
            int col = (u & 3) * 128 + lane;
            const float4* p0 = F + (size_t)dd.x * D4 + col;
            const float4* p1 = F + (size_t)dd.y * D4 + col;
            float4 a0 = __ldg(p0),      a1 = __ldg(p0 + 32),
                   a2 = __ldg(p0 + 64), a3 = __ldg(p0 + 96);
            float4 c0 = __ldg(p1),      c1 = __ldg(p1 + 32),
                   c2 = __ldg(p1 + 64), c3 = __ldg(p1 + 96);
            facc += sl1_4_half(a0, c0) + sl1_4_half(a1, c1) +
                    sl1_4_half(a2, c2) + sl1_4_half(a3, c3);
            dd = ddn; u = un;
        }
    }

    // ---- reduction: warp -> CTA -> g_partial -------------------------------
#pragma unroll
    for (int o = 16; o; o >>= 1)
        facc += __shfl_down_sync(0xffffffffu, facc, o);
    if (lane == 0) wsum[t >> 5] = facc;
    __syncthreads();
    if (t == 0) {
        float tot = 0.f;
#pragma unroll
        for (int w = 0; w < TPB / 32; w++) tot += wsum[w];
        g_partial[blockIdx.x] = (double)tot;
    }

    // last-block final reduction + scratch cleanup for next graph replay
    if (t == 0) {
        __threadfence();
        s_last = (atomicAdd(&g_done, 1) == NBLK - 1);
    }
    __syncthreads();
    if (!s_last) return;
    __threadfence();

    __shared__ double red[TPB];
    double local = 0.0;
    for (int i = t; i < NBLK; i += TPB) local += g_partial[i];
    red[t] = local;
    __syncthreads();
    for (int o = TPB / 2; o; o >>= 1) {
        if (t < o) red[t] += red[t + o];
        __syncthreads();
    }
    if (t == 0) {
        out[0] = (float)(red[0] / ((double)N_ROWS * (double)D));
        g_done = 0; g_n2 = 0; g_n3 = 0; g_n4 = 0; g_nbig = 0;
        g_ready = 0;
    }
    for (int i = t; i < S; i += TPB) g_count[i] = 0;   // restore invariant
}

extern "C" void kernel_launch(void* const* d_in, const int* in_sizes, int n_in,
                              void* d_out, int out_size) {
    const float* feats = (const float*)d_in[0];
    const int*   lab32 = (const int*)d_in[1];
    const int*   cam32 = (const int*)d_in[2];
    float* out = (float*)d_out;

    k_all<<<NBLK, TPB>>>(feats, lab32, cam32, out);   // single launch
}

// round 16
// speedup vs baseline: 1.0626x; 1.0626x over previous
#include <cuda_runtime.h>

#define N_ROWS 16384
#define D      2048
#define D4     (D / 4)              // 512 float4 per row
#define NUM_CAMS   8
#define S      8192                 // 1024 labels x 8 cams
#define SLOT_CAP 24                 // P(Poisson(2) > 24) ~ 1e-16; fallback exists
#define TPB    256
#define NBLK_PREP 64                // one per SM -> trivially co-resident
#define NBLK_MAIN 592               // 148 SMs x 4 CTAs (regs ~56-64) -> one wave
#define NWARPS (NBLK_MAIN * (TPB / 32))

// ---- scratch (device globals; invariant: counters zero at entry, restored
// ---- by k_main's last block after every run) ----
__device__ int      g_count[S];
__device__ int      g_slots[S * SLOT_CAP];
__device__ int      g_seg[N_ROWS];
__device__ int4     g_du[S];        // unified cnt 2..4 descriptors (padded)
__device__ int      g_big[S];       // seg ids with cnt >= 5
__device__ int      g_ndu, g_nbig;
__device__ int      g_done;
__device__ double   g_partial[NBLK_MAIN];
__device__ int      g_bar_count;    // stays 0 between runs
__device__ unsigned g_bar_gen;      // monotonically grows; never reset

// Barrier among NBLK_PREP (=64) blocks only. Safe: 64 <= 148 SMs, sole kernel
// in this graph node -> all resident.
__device__ __forceinline__ void prep_barrier() {
    __syncthreads();
    if (threadIdx.x == 0) {
        unsigned gen = *(volatile unsigned*)&g_bar_gen;   // read BEFORE arrive
        __threadfence();
        if (atomicAdd(&g_bar_count, 1) == NBLK_PREP - 1) {
            g_bar_count = 0;
            __threadfence();
            atomicAdd(&g_bar_gen, 1u);
        } else {
            while (*(volatile unsigned*)&g_bar_gen == gen) { }
        }
        __threadfence();
    }
    __syncthreads();
}

// ---------------------------------------------------------------------------
// K_PREP: 64 blocks x 256 threads = 16384 threads.
// Phase A: int64/int32 probe + per-row seg id + slot insertion (1 row/thread).
// 64-block barrier. Phase B: pack unified padded descriptors (cnt 2..4) +
// big list (cnt >= 5). Padding dups r0 so k_main's loads are unconditional.
// ---------------------------------------------------------------------------
__global__ __launch_bounds__(TPB) void k_prep(const int* __restrict__ lab32,
                                              const int* __restrict__ cam32) {
    __shared__ int s_any;
    int t = threadIdx.x;
    if (t == 0) s_any = 0;
    __syncthreads();
    // Odd int32 words of little-endian int64 cam_ids (values 0..7) are all 0;
    // index 2t+1 < 512 is in-bounds under both layouts.
    int probe = cam32[2 * t + 1];
#pragma unroll
    for (int o = 16; o; o >>= 1) probe |= __shfl_xor_sync(0xffffffffu, probe, o);
    if ((t & 31) == 0 && probe) atomicOr(&s_any, 1);
    __syncthreads();
    int stride = s_any ? 1 : 2;            // int32 : int64

    int gtid = blockIdx.x * TPB + t;       // 0 .. 16383 == N_ROWS
    {
        int seg = lab32[gtid * stride] * NUM_CAMS + cam32[gtid * stride];
        g_seg[gtid] = seg;
        int pos = atomicAdd(&g_count[seg], 1);
        if (pos < SLOT_CAP) g_slots[seg * SLOT_CAP + pos] = gtid;
    }

    prep_barrier();

    if (gtid < S) {
        int cnt = g_count[gtid];
        if (cnt >= 2) {
            const int* sl = g_slots + gtid * SLOT_CAP;
            if (cnt <= 4) {
                int r0 = sl[0];
                int4 d;
                d.x = r0;
                d.y = sl[1];
                d.z = (cnt > 2) ? sl[2] : r0;
                d.w = ((cnt > 3) ? sl[3] : r0) | (cnt << 16);
                g_du[atomicAdd(&g_ndu, 1)] = d;
            } else {
                g_big[atomicAdd(&g_nbig, 1)] = gtid;
            }
        }
    }
}

__device__ __forceinline__ float sl1(float d) {
    float ad = fabsf(d);
    return ad < 1.0f ? 0.5f * d * d : ad - 0.5f;
}
__device__ __forceinline__ float sl1_4(float4 a, float4 m) {
    return sl1(a.x - m.x) + sl1(a.y - m.y) + sl1(a.z - m.z) + sl1(a.w - m.w);
}
__device__ __forceinline__ void acc4(float4& s, float4 a) {
    s.x += a.x; s.y += a.y; s.z += a.z; s.w += a.w;
}
__device__ __forceinline__ void pf_l2(const float4* p) {
    asm volatile("prefetch.global.L2 [%0];" :: "l"(p));
}

// ---------------------------------------------------------------------------
// K_MAIN: BIG phase (cnt>=5, rare) then ONE unified loop over cnt 2..4 items
// (256-col chunks). The unified loop software-pipelines:
//   - descriptor loaded 2 items ahead,
//   - rows of the NEXT item prefetched into L2 while the CURRENT item's
//     DRAM loads are in flight -> next item's loads hit L2 (~250cyc vs ~600).
// Unconditional 8 LDG.128 per item (pads dup r0 -> L1 hits); masked math.
// Last block: final reduction, output, scratch reset.
// ---------------------------------------------------------------------------
__global__ __launch_bounds__(TPB) void k_main(const float* __restrict__ feats,
                                              float* __restrict__ out) {
    __shared__ float wsum[TPB / 32];
    __shared__ bool  s_last;
    int t = threadIdx.x;
    int lane = t & 31;
    int gw = blockIdx.x * (TPB / 32) + (t >> 5);
    const float4* __restrict__ F = (const float4*)feats;
    float facc = 0.f;

    // ---- BIG: cnt >= 5, two-pass via slots (pass 2 = L1 hit), 256-col items
    {
        int nitems = g_nbig * 8;
        for (int u = gw; u < nitems; u += NWARPS) {
            int seg = g_big[u >> 3];
            int col = (u & 7) * 64 + lane;
            int cnt = g_count[seg];
            if (cnt <= SLOT_CAP) {
                const int* sl = g_slots + seg * SLOT_CAP;
                float4 s0 = make_float4(0.f, 0.f, 0.f, 0.f);
                float4 s1 = make_float4(0.f, 0.f, 0.f, 0.f);
                for (int k = 0; k < cnt; k++) {
                    const float4* p = F + (size_t)sl[k] * D4 + col;
                    acc4(s0, __ldg(p)); acc4(s1, __ldg(p + 32));
                }
                float inv = 1.0f / (float)cnt;
                float4 m0 = make_float4(s0.x*inv, s0.y*inv, s0.z*inv, s0.w*inv);
                float4 m1 = make_float4(s1.x*inv, s1.y*inv, s1.z*inv, s1.w*inv);
                for (int k = 0; k < cnt; k++) {
                    const float4* p = F + (size_t)sl[k] * D4 + col;
                    facc += sl1_4(__ldg(p), m0) + sl1_4(__ldg(p + 32), m1);
                }
            } else {                                   // ~1e-16 fallback
                float4 s0 = make_float4(0.f, 0.f, 0.f, 0.f);
                float4 s1 = make_float4(0.f, 0.f, 0.f, 0.f);
                for (int r = 0; r < N_ROWS; r++)
                    if (g_seg[r] == seg) {
                        const float4* p = F + (size_t)r * D4 + col;
                        acc4(s0, __ldg(p)); acc4(s1, __ldg(p + 32));
                    }
                float inv = 1.0f / (float)cnt;
                float4 m0 = make_float4(s0.x*inv, s0.y*inv, s0.z*inv, s0.w*inv);
                float4 m1 = make_float4(s1.x*inv, s1.y*inv, s1.z*inv, s1.w*inv);
                for (int r = 0; r < N_ROWS; r++)
                    if (g_seg[r] == seg) {
                        const float4* p = F + (size_t)r * D4 + col;
                        facc += sl1_4(__ldg(p), m0) + sl1_4(__ldg(p + 32), m1);
                    }
            }
        }
    }

    // ---- UNIFIED: cnt 2..4, pipelined with L2 prefetch ---------------------
    {
        int nitems = g_ndu * 8;                        // 8 x 256-col chunks
        int u = gw;
        int4 d0 = (u < nitems) ? g_du[u >> 3] : make_int4(0, 0, 0, 0);
        int un0 = u + NWARPS;
        int4 d1 = (un0 < nitems) ? g_du[un0 >> 3] : d0;

        while (u < nitems) {
            int un = u + NWARPS;

            // 1) prefetch NEXT item's rows into L2 (zero registers consumed;
            //    lead time = this item's DRAM stall window)
            if (un < nitems) {
                int cn   = d1.w >> 16;
                int coln = (un & 7) * 64 + lane;
                const float4* q0 = F + (size_t)d1.x * D4 + coln;
                const float4* q1 = F + (size_t)d1.y * D4 + coln;
                pf_l2(q0); pf_l2(q0 + 32);
                pf_l2(q1); pf_l2(q1 + 32);
                if (cn > 2) {
                    const float4* q2 = F + (size_t)d1.z * D4 + coln;
                    pf_l2(q2); pf_l2(q2 + 32);
                }
                if (cn > 3) {
                    const float4* q3 = F + (size_t)(d1.w & 0xFFFF) * D4 + coln;
                    pf_l2(q3); pf_l2(q3 + 32);
                }
            }
            // 2) descriptor two ahead (hides its own latency)
            int un2 = u + 2 * NWARPS;
            int4 d2 = (un2 < nitems) ? g_du[un2 >> 3] : d1;

            // 3) current item: unconditional 8 loads (pads dup r0 -> L1 hit)
            int cnt = d0.w >> 16;
            int r3  = d0.w & 0xFFFF;
            int col = (u & 7) * 64 + lane;
            const float4* p0 = F + (size_t)d0.x * D4 + col;
            const float4* p1 = F + (size_t)d0.y * D4 + col;
            const float4* p2 = F + (size_t)d0.z * D4 + col;
            const float4* p3 = F + (size_t)r3   * D4 + col;
            float4 a0 = __ldg(p0), b0 = __ldg(p0 + 32);
            float4 a1 = __ldg(p1), b1 = __ldg(p1 + 32);
            float4 a2 = __ldg(p2), b2 = __ldg(p2 + 32);
            float4 a3 = __ldg(p3), b3 = __ldg(p3 + 32);

            float4 s0 = make_float4(a0.x + a1.x, a0.y + a1.y, a0.z + a1.z, a0.w + a1.w);
            float4 s1 = make_float4(b0.x + b1.x, b0.y + b1.y, b0.z + b1.z, b0.w + b1.w);
            if (cnt > 2) { acc4(s0, a2); acc4(s1, b2); }
            if (cnt > 3) { acc4(s0, a3); acc4(s1, b3); }
            float inv = 1.0f / (float)cnt;
            float4 m0 = make_float4(s0.x*inv, s0.y*inv, s0.z*inv, s0.w*inv);
            float4 m1 = make_float4(s1.x*inv, s1.y*inv, s1.z*inv, s1.w*inv);

            facc += sl1_4(a0, m0) + sl1_4(a1, m0);
            facc += sl1_4(b0, m1) + sl1_4(b1, m1);
            if (cnt > 2) facc += sl1_4(a2, m0) + sl1_4(b2, m1);
            if (cnt > 3) facc += sl1_4(a3, m0) + sl1_4(b3, m1);

            d0 = d1; d1 = d2; u = un;
        }
    }

    // ---- reduction: warp -> CTA -> g_partial -------------------------------
#pragma unroll
    for (int o = 16; o; o >>= 1)
        facc += __shfl_down_sync(0xffffffffu, facc, o);
    if (lane == 0) wsum[t >> 5] = facc;
    __syncthreads();
    if (t == 0) {
        float tot = 0.f;
#pragma unroll
        for (int w = 0; w < TPB / 32; w++) tot += wsum[w];
        g_partial[blockIdx.x] = (double)tot;
    }

    // last-block final reduction + scratch cleanup for next graph replay
    if (t == 0) {
        __threadfence();
        s_last = (atomicAdd(&g_done, 1) == NBLK_MAIN - 1);
    }
    __syncthreads();
    if (!s_last) return;
    __threadfence();

    __shared__ double red[TPB];
    double local = 0.0;
    for (int i = t; i < NBLK_MAIN; i += TPB) local += g_partial[i];
    red[t] = local;
    __syncthreads();
    for (int o = TPB / 2; o; o >>= 1) {
        if (t < o) red[t] += red[t + o];
        __syncthreads();
    }
    if (t == 0) {
        out[0] = (float)(red[0] / ((double)N_ROWS * (double)D));
        g_done = 0; g_ndu = 0; g_nbig = 0;
    }
    for (int i = t; i < S; i += TPB) g_count[i] = 0;   // restore invariant
}

extern "C" void kernel_launch(void* const* d_in, const int* in_sizes, int n_in,
                              void* d_out, int out_size) {
    const float* feats = (const float*)d_in[0];
    const int*   lab32 = (const int*)d_in[1];
    const int*   cam32 = (const int*)d_in[2];
    float* out = (float*)d_out;

    k_prep<<<NBLK_PREP, TPB>>>(lab32, cam32);   // build + pack, one launch
    k_main<<<NBLK_MAIN, TPB>>>(feats, out);
}